// round 1
// baseline (speedup 1.0000x reference)
#include <cuda_runtime.h>
#include <cuda_bf16.h>
#include <stdint.h>

// ApplyRotary: T=32768 tokens, H=32 heads, D=128, ROPE_DIM=64.
// out[t,h,d<32]   =  x[d]*cos[d] - x[d+32]*sin[d]
// out[t,h,32<=d<64]=  x[d]*cos[d] + x[d-32]*sin[d]
// out[t,h,d>=64]  =  x[d]
// off = t - cu_seqlen[seg], seg = searchsorted_right(cu, t) - 1.
//
// One warp per (t,h) row (512 B). Lane l handles floats [4l, 4l+4).
// Rope pair exchanged via shfl.xor(8). Pure HBM-bound kernel.

#define N_TOK   32768
#define N_HEAD  32
#define N_ROWS  (N_TOK * N_HEAD)
#define ROPE    64

__global__ __launch_bounds__(256) void rope_kernel(
    const float* __restrict__ in,
    const float* __restrict__ sin_c,
    const float* __restrict__ cos_c,
    const int*   __restrict__ cu,
    float*       __restrict__ out)
{
    const int gw   = (int)((blockIdx.x * blockDim.x + threadIdx.x) >> 5);
    const int lane = threadIdx.x & 31;
    if (gw >= N_ROWS) return;

    const int t = gw >> 5;  // H = 32

    // Branchless binary search: largest idx in [0,16] with cu[idx] <= t.
    int lo = 0;
#pragma unroll
    for (int half = 16; half > 0; half >>= 1) {
        int mid = lo + half;
        if (mid <= 16 && __ldg(cu + mid) <= t) lo = mid;
    }
    const int off = t - __ldg(cu + lo);

    // Load this lane's float4 of the row.
    const float4 v = __ldg(reinterpret_cast<const float4*>(in) + (size_t)gw * 32 + lane);

    // Exchange rope halves: lane l <-> lane l^8 (only meaningful for lanes 0..15).
    float4 q;
    q.x = __shfl_xor_sync(0xffffffffu, v.x, 8);
    q.y = __shfl_xor_sync(0xffffffffu, v.y, 8);
    q.z = __shfl_xor_sync(0xffffffffu, v.z, 8);
    q.w = __shfl_xor_sync(0xffffffffu, v.w, 8);

    float4 r = v;
    if (lane < 16) {
        const float4 s4 = __ldg(reinterpret_cast<const float4*>(sin_c + (size_t)off * ROPE) + lane);
        const float4 c4 = __ldg(reinterpret_cast<const float4*>(cos_c + (size_t)off * ROPE) + lane);
        const float sg = (lane < 8) ? -1.0f : 1.0f;
        r.x = fmaf(sg * q.x, s4.x, v.x * c4.x);
        r.y = fmaf(sg * q.y, s4.y, v.y * c4.y);
        r.z = fmaf(sg * q.z, s4.z, v.z * c4.z);
        r.w = fmaf(sg * q.w, s4.w, v.w * c4.w);
    }

    reinterpret_cast<float4*>(out)[(size_t)gw * 32 + lane] = r;
}

extern "C" void kernel_launch(void* const* d_in, const int* in_sizes, int n_in,
                              void* d_out, int out_size)
{
    const float* in    = (const float*)d_in[0];
    const float* sin_c = (const float*)d_in[1];
    const float* cos_c = (const float*)d_in[2];
    const int*   cu    = (const int*)  d_in[3];
    float*       out   = (float*)d_out;

    // 1 warp per row, 8 warps per block.
    const int blocks = N_ROWS / 8;   // 131072
    rope_kernel<<<blocks, 256>>>(in, sin_c, cos_c, cu, out);
}

// round 2
// speedup vs baseline: 1.2215x; 1.2215x over previous
#include <cuda_runtime.h>
#include <cuda_bf16.h>
#include <stdint.h>

// ApplyRotary: T=32768 tokens, H=32 heads, D=128, ROPE_DIM=64.
// out[t,h,d<32]    =  x[d]*cos[d] - x[d+32]*sin[d]
// out[t,h,32<=d<64]=  x[d]*cos[d] + x[d-32]*sin[d]
// out[t,h,d>=64]   =  x[d]
//
// One WARP per TOKEN: binary search + sin/cos fetched once, reused for all
// 32 heads. Lane l covers floats [4l,4l+4) of each 128-float row; the rope
// partner (d +/- 32) sits in lane l^8 -> shfl.xor(8). 4 rows loaded per
// chunk, outer unroll 2 => up to 8 LDG.128 in flight per warp.

#define N_TOK   32768
#define N_HEAD  32
#define ROPE    64

__global__ __launch_bounds__(256, 5) void rope_kernel(
    const float* __restrict__ in,
    const float* __restrict__ sin_c,
    const float* __restrict__ cos_c,
    const int*   __restrict__ cu,
    float*       __restrict__ out)
{
    const int warp = threadIdx.x >> 5;
    const int lane = threadIdx.x & 31;
    const int t    = blockIdx.x * 8 + warp;   // one token per warp

    // Branchless binary search: largest idx in [0,16] with cu[idx] <= t.
    int lo = 0;
#pragma unroll
    for (int half = 16; half > 0; half >>= 1) {
        int mid = lo + half;
        if (mid <= 16 && __ldg(cu + mid) <= t) lo = mid;
    }
    const int off = t - __ldg(cu + lo);

    // sin/cos for this token, held in registers for all 32 heads.
    float4 s4 = make_float4(0.f, 0.f, 0.f, 0.f);
    float4 c4 = s4;
    if (lane < 16) {
        s4 = __ldg(reinterpret_cast<const float4*>(sin_c + (size_t)off * ROPE) + lane);
        c4 = __ldg(reinterpret_cast<const float4*>(cos_c + (size_t)off * ROPE) + lane);
    }
    const float sg = (lane < 8) ? -1.0f : 1.0f;

    const float4* in4  = reinterpret_cast<const float4*>(in) + (size_t)t * (N_HEAD * 32) + lane;
    float4*       out4 = reinterpret_cast<float4*>(out)      + (size_t)t * (N_HEAD * 32) + lane;

#pragma unroll 2
    for (int h0 = 0; h0 < N_HEAD; h0 += 4) {
        float4 v[4];
#pragma unroll
        for (int i = 0; i < 4; i++)
            v[i] = __ldg(in4 + (size_t)(h0 + i) * 32);

#pragma unroll
        for (int i = 0; i < 4; i++) {
            float4 q;
            q.x = __shfl_xor_sync(0xffffffffu, v[i].x, 8);
            q.y = __shfl_xor_sync(0xffffffffu, v[i].y, 8);
            q.z = __shfl_xor_sync(0xffffffffu, v[i].z, 8);
            q.w = __shfl_xor_sync(0xffffffffu, v[i].w, 8);

            float4 r = v[i];
            if (lane < 16) {
                r.x = fmaf(sg * q.x, s4.x, v[i].x * c4.x);
                r.y = fmaf(sg * q.y, s4.y, v[i].y * c4.y);
                r.z = fmaf(sg * q.z, s4.z, v[i].z * c4.z);
                r.w = fmaf(sg * q.w, s4.w, v[i].w * c4.w);
            }
            out4[(size_t)(h0 + i) * 32] = r;
        }
    }
}

extern "C" void kernel_launch(void* const* d_in, const int* in_sizes, int n_in,
                              void* d_out, int out_size)
{
    const float* in    = (const float*)d_in[0];
    const float* sin_c = (const float*)d_in[1];
    const float* cos_c = (const float*)d_in[2];
    const int*   cu    = (const int*)  d_in[3];
    float*       out   = (float*)d_out;

    // 1 warp per token, 8 warps per block.
    const int blocks = N_TOK / 8;   // 4096
    rope_kernel<<<blocks, 256>>>(in, sin_c, cos_c, cu, out);
}